// round 1
// baseline (speedup 1.0000x reference)
#include <cuda_runtime.h>
#include <math.h>

#define BB 2
#define CC 512
#define PP 4096
#define NHEAD 8
#define GG 32
#define CPG 16
#define EPSV 1e-5f

// scratch (device globals: allocation-free per harness rules)
__device__ float g_h[BB * CC * PP];        // groupnorm output        (16 MB)
__device__ float g_qkv[BB * 3 * CC * PP];  // qkv projections         (50 MB)
__device__ float g_att[BB * CC * PP];      // attention output        (16 MB)

// ---------------------------------------------------------------------------
// GroupNorm: one block per (batch, group). 16 channels x 4096 = 65536 elems.
// ---------------------------------------------------------------------------
__global__ __launch_bounds__(256) void gn_kernel(const float* __restrict__ x,
                                                 const float* __restrict__ gw,
                                                 const float* __restrict__ gb,
                                                 float* __restrict__ out) {
    int bg = blockIdx.x;
    int b = bg / GG, g = bg % GG;
    const float4* xp = (const float4*)(x + ((size_t)b * CC + g * CPG) * PP);
    float4* op = (float4*)(out + ((size_t)b * CC + g * CPG) * PP);
    const int N4 = CPG * PP / 4;  // 16384
    float s = 0.f, s2 = 0.f;
    for (int i = threadIdx.x; i < N4; i += 256) {
        float4 v = xp[i];
        s += v.x + v.y + v.z + v.w;
        s2 += v.x * v.x + v.y * v.y + v.z * v.z + v.w * v.w;
    }
    __shared__ float rs[256], rs2[256];
    rs[threadIdx.x] = s; rs2[threadIdx.x] = s2;
    __syncthreads();
    for (int o = 128; o > 0; o >>= 1) {
        if (threadIdx.x < o) { rs[threadIdx.x] += rs[threadIdx.x + o]; rs2[threadIdx.x] += rs2[threadIdx.x + o]; }
        __syncthreads();
    }
    __shared__ float smean, srstd;
    if (threadIdx.x == 0) {
        float mean = rs[0] / (float)(CPG * PP);
        float var = rs2[0] / (float)(CPG * PP) - mean * mean;
        smean = mean;
        srstd = rsqrtf(var + EPSV);
    }
    __syncthreads();
    float mean = smean, rstd = srstd;
    for (int i = threadIdx.x; i < N4; i += 256) {
        int c = g * CPG + (i >> 10);   // (i*4)/4096
        float ga = gw[c] * rstd, be = gb[c];
        float4 v = xp[i];
        v.x = (v.x - mean) * ga + be;
        v.y = (v.y - mean) * ga + be;
        v.z = (v.z - mean) * ga + be;
        v.w = (v.w - mean) * ga + be;
        op[i] = v;
    }
}

// ---------------------------------------------------------------------------
// Generic channel GEMM: Out[b][o][p] = sum_c W[o][c] * In[b][c][p]
//                        (+ bias[o] + resid[b][o][p] when provided)
// 64x64 output tile per block, K-tile 16, 256 threads, 4x4 micro-tile.
// ---------------------------------------------------------------------------
__global__ __launch_bounds__(256) void gemm64(const float* __restrict__ W,
                                              const float* __restrict__ In,
                                              float* __restrict__ Out,
                                              const float* __restrict__ bias,
                                              const float* __restrict__ resid,
                                              int Mrows) {
    __shared__ float Ws[16][64];
    __shared__ float Hs[16][64];
    int tid = threadIdx.x;
    int b = blockIdx.z;
    int o0 = blockIdx.y << 6, p0 = blockIdx.x << 6;
    const float* Wp = W + (size_t)o0 * CC;
    const float* Ip = In + (size_t)b * CC * PP + p0;
    int ty = tid >> 4, tx = tid & 15;
    int wrow = tid >> 2, wq = (tid & 3) << 2;
    int hk = tid >> 4, hq = (tid & 15) << 2;
    float acc[4][4] = {};
    for (int k0 = 0; k0 < CC; k0 += 16) {
        __syncthreads();
        float4 w4 = *(const float4*)(Wp + (size_t)wrow * CC + k0 + wq);
        Ws[wq + 0][wrow] = w4.x;
        Ws[wq + 1][wrow] = w4.y;
        Ws[wq + 2][wrow] = w4.z;
        Ws[wq + 3][wrow] = w4.w;
        *(float4*)&Hs[hk][hq] = *(const float4*)(Ip + (size_t)(k0 + hk) * PP + hq);
        __syncthreads();
#pragma unroll
        for (int kk = 0; kk < 16; kk++) {
            float4 a = *(float4*)&Ws[kk][ty << 2];
            float4 h = *(float4*)&Hs[kk][tx << 2];
            const float* af = (const float*)&a;
            const float* hf = (const float*)&h;
#pragma unroll
            for (int r = 0; r < 4; r++)
#pragma unroll
                for (int u = 0; u < 4; u++) acc[r][u] += af[r] * hf[u];
        }
    }
#pragma unroll
    for (int r = 0; r < 4; r++) {
        int o = o0 + (ty << 2) + r;
        float bv = bias ? bias[o] : 0.f;
        size_t off = ((size_t)b * Mrows + o) * PP + p0 + (tx << 2);
        float4 v = make_float4(acc[r][0] + bv, acc[r][1] + bv, acc[r][2] + bv, acc[r][3] + bv);
        if (resid) {
            float4 rr = *(const float4*)(resid + off);
            v.x += rr.x; v.y += rr.y; v.z += rr.z; v.w += rr.w;
        }
        *(float4*)(Out + off) = v;
    }
}

// ---------------------------------------------------------------------------
// Flash attention. Per block: one (bh, 64-row query tile).
// qkv layout: [b][3C][P]; head nh uses channels [nh*192, nh*192+192):
//   q rows +0..63, k rows +64..127, v rows +128..191.
// Online softmax stats (m, l) live in registers, reduced across the 16 tx
// lanes of each half-warp via shfl (rows are replicated over tx).
// smem: qs(16KB) + kv(16KB, K then V reuse) + ss(16KB) = exactly 48KB static.
// ---------------------------------------------------------------------------
__global__ __launch_bounds__(256) void attn_kernel(const float* __restrict__ qkv,
                                                   float* __restrict__ att) {
    __shared__ float qs[64 * 64];
    __shared__ float kv[64 * 64];
    __shared__ float ss[64 * 64];
    int bh = blockIdx.y;
    int i0 = blockIdx.x << 6;
    int b = bh >> 3, nh = bh & 7;
    const float* qb = qkv + ((size_t)b * 3 * CC + nh * 192) * PP;
    const float* kb = qb + (size_t)64 * PP;
    const float* vb = qb + (size_t)128 * PP;
    int tid = threadIdx.x;
    int ty = tid >> 4, tx = tid & 15;
    const int ii = ty << 2;
    const int jj = tx << 2;

    // load Q tile (scaled by 1/8 = scale^2): qs[c][i]
#pragma unroll
    for (int it = 0; it < 4; it++) {
        int idx = tid + it * 256;
        int c = idx >> 4, q4 = (idx & 15) << 2;
        float4 v = *(const float4*)(qb + (size_t)c * PP + i0 + q4);
        v.x *= 0.125f; v.y *= 0.125f; v.z *= 0.125f; v.w *= 0.125f;
        *(float4*)&qs[c * 64 + q4] = v;
    }

    float O[4][4] = {};
    float mrow[4], lrow[4];
#pragma unroll
    for (int r = 0; r < 4; r++) { mrow[r] = -INFINITY; lrow[r] = 0.f; }

    for (int j0 = 0; j0 < PP; j0 += 64) {
        __syncthreads();  // prev PV done with ss/kv
        // load K tile: kv[c][j]
#pragma unroll
        for (int it = 0; it < 4; it++) {
            int idx = tid + it * 256;
            int c = idx >> 4, q4 = (idx & 15) << 2;
            *(float4*)&kv[c * 64 + q4] = *(const float4*)(kb + (size_t)c * PP + j0 + q4);
        }
        __syncthreads();

        // S = (Q*s)(K*s)^T for this 64x64 tile, 4x4 per thread
        float s[4][4] = {};
#pragma unroll 16
        for (int c = 0; c < 64; c++) {
            float4 a = *(float4*)&qs[c * 64 + ii];
            float4 bk = *(float4*)&kv[c * 64 + jj];
            const float* af = (const float*)&a;
            const float* bf = (const float*)&bk;
#pragma unroll
            for (int r = 0; r < 4; r++)
#pragma unroll
                for (int u = 0; u < 4; u++) s[r][u] += af[r] * bf[u];
        }

        // online softmax: per-row reduce over the 16 tx lanes (half-warp)
#pragma unroll
        for (int r = 0; r < 4; r++) {
            float mx = fmaxf(fmaxf(s[r][0], s[r][1]), fmaxf(s[r][2], s[r][3]));
            mx = fmaxf(mx, __shfl_xor_sync(0xffffffffu, mx, 1));
            mx = fmaxf(mx, __shfl_xor_sync(0xffffffffu, mx, 2));
            mx = fmaxf(mx, __shfl_xor_sync(0xffffffffu, mx, 4));
            mx = fmaxf(mx, __shfl_xor_sync(0xffffffffu, mx, 8));
            float mnew = fmaxf(mrow[r], mx);
            float alpha = __expf(mrow[r] - mnew);
            float sum = 0.f;
#pragma unroll
            for (int u = 0; u < 4; u++) {
                s[r][u] = __expf(s[r][u] - mnew);
                sum += s[r][u];
            }
            sum += __shfl_xor_sync(0xffffffffu, sum, 1);
            sum += __shfl_xor_sync(0xffffffffu, sum, 2);
            sum += __shfl_xor_sync(0xffffffffu, sum, 4);
            sum += __shfl_xor_sync(0xffffffffu, sum, 8);
            lrow[r] = lrow[r] * alpha + sum;
            mrow[r] = mnew;
#pragma unroll
            for (int u = 0; u < 4; u++) O[r][u] *= alpha;
        }
        // write P tile
#pragma unroll
        for (int r = 0; r < 4; r++)
            *(float4*)&ss[(ii + r) * 64 + jj] = make_float4(s[r][0], s[r][1], s[r][2], s[r][3]);
        __syncthreads();  // ss visible; all K reads done -> kv reusable

        // load V tile transposed with float4-granular XOR swizzle:
        //   vs[j][c] stored at  j*64 + ((c/4) ^ (j&15))*4 + (c&3)
#pragma unroll
        for (int it = 0; it < 4; it++) {
            int idx = tid + it * 256;
            int c = idx >> 4, q = (idx & 15) << 2;
            float4 v = *(const float4*)(vb + (size_t)c * PP + j0 + q);
            int c4 = c >> 2, cm = c & 3;
            kv[(q + 0) * 64 + ((c4 ^ ((q + 0) & 15)) << 2) + cm] = v.x;
            kv[(q + 1) * 64 + ((c4 ^ ((q + 1) & 15)) << 2) + cm] = v.y;
            kv[(q + 2) * 64 + ((c4 ^ ((q + 2) & 15)) << 2) + cm] = v.z;
            kv[(q + 3) * 64 + ((c4 ^ ((q + 3) & 15)) << 2) + cm] = v.w;
        }
        __syncthreads();

        // O[i][c] += sum_j P[i][j] * V[c][j]
#pragma unroll 4
        for (int j = 0; j < 64; j += 4) {
            float4 A[4], Bv[4];
#pragma unroll
            for (int r = 0; r < 4; r++) A[r] = *(float4*)&ss[(ii + r) * 64 + j];
#pragma unroll
            for (int t = 0; t < 4; t++)
                Bv[t] = *(float4*)&kv[(j + t) * 64 + ((tx ^ ((j + t) & 15)) << 2)];
            const float* Af = (const float*)A;
            const float* Bf = (const float*)Bv;
#pragma unroll
            for (int t = 0; t < 4; t++)
#pragma unroll
                for (int r = 0; r < 4; r++)
#pragma unroll
                    for (int u = 0; u < 4; u++) O[r][u] += Af[r * 4 + t] * Bf[t * 4 + u];
        }
    }

    // finalize: divide by l, store to att[b][nh*64 + c][i]
#pragma unroll
    for (int r = 0; r < 4; r++) {
        float inv = 1.f / lrow[r];
#pragma unroll
        for (int u = 0; u < 4; u++) O[r][u] *= inv;
    }
    float* ab = att + ((size_t)b * CC + nh * 64) * PP;
#pragma unroll
    for (int u = 0; u < 4; u++) {
        int c = jj + u;
        *(float4*)(ab + (size_t)c * PP + i0 + ii) =
            make_float4(O[0][u], O[1][u], O[2][u], O[3][u]);
    }
}

// ---------------------------------------------------------------------------
extern "C" void kernel_launch(void* const* d_in, const int* in_sizes, int n_in,
                              void* d_out, int out_size) {
    const float* x = (const float*)d_in[0];
    const float* qkv_w = (const float*)d_in[1];
    const float* proj_w = (const float*)d_in[2];
    const float* proj_b = (const float*)d_in[3];
    const float* gn_w = (const float*)d_in[4];
    const float* gn_b = (const float*)d_in[5];
    float* out = (float*)d_out;

    float *hp, *qkvp, *attp;
    cudaGetSymbolAddress((void**)&hp, g_h);
    cudaGetSymbolAddress((void**)&qkvp, g_qkv);
    cudaGetSymbolAddress((void**)&attp, g_att);

    // 1) GroupNorm
    gn_kernel<<<BB * GG, 256>>>(x, gn_w, gn_b, hp);
    // 2) QKV 1x1 conv: [1536x512] @ [512x4096] per batch
    gemm64<<<dim3(PP / 64, (3 * CC) / 64, BB), 256>>>(qkv_w, hp, qkvp, nullptr, nullptr, 3 * CC);
    // 3) flash attention over 16 (b,head) pairs, 64 query tiles each
    attn_kernel<<<dim3(PP / 64, BB * NHEAD), 256>>>(qkvp, attp);
    // 4) proj 1x1 conv + bias + residual
    gemm64<<<dim3(PP / 64, CC / 64, BB), 256>>>(proj_w, attp, out, proj_b, x, CC);
}